// round 11
// baseline (speedup 1.0000x reference)
#include <cuda_runtime.h>
#include <cstdint>
#include <cstddef>

#define BB 1024
#define TT 1024
#define NN 34
#define BPB 2
#define FWD_THREADS 192            // warps 0-2: chain (68 active); warps 3-5: bp (68 active)
#define FWD_BLOCKS  592            // 4 CTAs/SM balanced; tail clamps to b=1023 (idempotent)
#define LAG 2                      // bp processes step t-LAG

__device__ unsigned char g_bp[(size_t)BB * TT * NN];
__device__ int g_idx[BB];

__device__ __forceinline__ unsigned long long addx2(unsigned long long a, unsigned long long b) {
    unsigned long long r;
    asm("add.rn.f32x2 %0, %1, %2;" : "=l"(r) : "l"(a), "l"(b));
    return r;
}
__device__ __forceinline__ unsigned long long packff(float f) {
    unsigned long long r; unsigned u = __float_as_uint(f);
    asm("mov.b64 %0, {%1, %1};" : "=l"(r) : "r"(u));
    return r;
}
__device__ __forceinline__ void unpk(unsigned long long v, float& lo, float& hi) {
    unsigned a, b;
    asm("mov.b64 {%0, %1}, %2;" : "=r"(a), "=r"(b) : "l"(v));
    lo = __uint_as_float(a); hi = __uint_as_float(b);
}

// Fused forward: chain warps run the (max,+) recurrence over an 8-slot smem
// ring; bp warps recompute candidates for step t-2 from the ring and emit the
// argmax via equality matching (identical f32x2 ops => bit-identical match).
__global__ __launch_bounds__(FWD_THREADS)
void viterbi_fused(const float* __restrict__ feat,
                   const float* __restrict__ trans,
                   float* __restrict__ out)
{
    const int tid = threadIdx.x;
    const bool is_chain = (tid < 68);
    const bool is_bp    = (tid >= 96 && tid < 96 + 68);
    const int g  = is_chain ? tid : (tid - 96);       // 0..67 within group
    const int bl = g / NN;
    const int j  = g % NN;
    int b = blockIdx.x * BPB + bl;
    if (b >= BB) b = BB - 1;

    // ring[slot = (x+1)&7] holds score row S_x ; fring[t&7] holds f_t
    __shared__ __align__(16) float ring[8][BPB][36];
    __shared__ float fring[8][BPB][NN];
    __shared__ float tend[NN];
    __shared__ float fin[BPB][NN];

    // trans row j packed (both groups need it)
    unsigned long long trp[17];
    if (is_chain || is_bp) {
#pragma unroll
        for (int i = 0; i < 17; i++) {
            unsigned lo = __float_as_uint(__ldg(trans + j * NN + 2 * i));
            unsigned hi = __float_as_uint(__ldg(trans + j * NN + 2 * i + 1));
            asm("mov.b64 %0, {%1, %2};" : "=l"(trp[i]) : "r"(lo), "r"(hi));
        }
    }
    if (tid < NN) tend[tid] = __ldg(trans + (NN - 1) * NN + tid);

    if (is_chain) ring[0][bl][j] = (j == NN - 2) ? 0.0f : -6969.0f;  // S_{-1}

    // chain-side feat prefetch ring (4-deep)
    const size_t fbase = (size_t)b * ((size_t)TT * NN) + j;
    const float* fp = feat + fbase;
    float fr[4];
    if (is_chain) {
#pragma unroll
        for (int u = 0; u < 4; u++) fr[u] = __ldg(fp + (size_t)u * NN);
    }
    fp += (size_t)4 * NN;

    unsigned char* bpp = g_bp + (size_t)b * ((size_t)TT * NN) + j;

    __syncthreads();

    // uniform loop: chain does step t (t<TT); bp does step tb=t-LAG (0<=tb<TT)
#pragma unroll 1
    for (int it = 0; it < TT + LAG + 2; it += 4) {
#pragma unroll
        for (int u = 0; u < 4; u++) {
            const int t = it + u;

            if (is_chain && t < TT) {
                float f = fr[u];
                float fn = 0.0f;
                if (t + 4 < TT) fn = __ldg(fp);
                fp += NN;
                fr[u] = fn;

                const ulonglong2* sp2 = (const ulonglong2*)&ring[t & 7][bl][0];
                unsigned long long ff = packff(f);

                float m[NN];
#pragma unroll
                for (int i = 0; i < 8; i++) {
                    ulonglong2 q = sp2[i];
                    unsigned long long v0 = addx2(addx2(q.x, ff), trp[2 * i]);
                    unsigned long long v1 = addx2(addx2(q.y, ff), trp[2 * i + 1]);
                    unpk(v0, m[4 * i], m[4 * i + 1]);
                    unpk(v1, m[4 * i + 2], m[4 * i + 3]);
                }
                {
                    unsigned long long q = *(const unsigned long long*)&ring[t & 7][bl][32];
                    unsigned long long v = addx2(addx2(q, ff), trp[16]);
                    unpk(v, m[32], m[33]);
                }
#pragma unroll
                for (int s = 1; s < NN; s <<= 1)
#pragma unroll
                    for (int k = 0; k + s < NN; k += (s << 1))
                        m[k] = fmaxf(m[k], m[k + s]);

                ring[(t + 1) & 7][bl][j] = m[0];
                fring[t & 7][bl][j] = f;
            }

            const int tb = t - LAG;
            if (is_bp && tb >= 0 && tb < TT) {
                const float tgt = ring[(tb + 1) & 7][bl][j];   // S_tb[j]
                const float f   = fring[tb & 7][bl][j];
                unsigned long long ff = packff(f);
                const unsigned long long* srow =
                    (const unsigned long long*)&ring[tb & 7][bl][0];  // S_{tb-1}

                int e[17];
#pragma unroll
                for (int i = 0; i < 17; i++) {
                    float c0, c1;
                    unsigned long long v = addx2(addx2(srow[i], ff), trp[i]);
                    unpk(v, c0, c1);
                    int lo = (c0 == tgt) ? (2 * i)     : 63;
                    int hi = (c1 == tgt) ? (2 * i + 1) : 63;
                    e[i] = lo < hi ? lo : hi;
                }
#pragma unroll
                for (int st = 1; st < 17; st <<= 1)
#pragma unroll
                    for (int k = 0; k + st < 17; k += (st << 1))
                        e[k] = e[k] < e[k + st] ? e[k] : e[k + st];

                bpp[(size_t)tb * NN] = (unsigned char)e[0];
            }

            __syncthreads();
        }
    }

    // termination (chain group)
    if (is_chain) fin[bl][j] = ring[TT & 7][bl][j] + tend[j];
    __syncthreads();
    if (is_chain && j == 0) {
        float bm = -3.4e38f; int bi = 0;
#pragma unroll
        for (int k = 0; k < NN; k++) {
            float v = fin[bl][k];
            if (v > bm) { bm = v; bi = k; }
        }
        out[b] = bm;
        g_idx[b] = bi;
    }
}

// Proven chase (~48 us): stage bp table in smem, thread 0 walks it.
__global__ __launch_bounds__(256)
void viterbi_back(float* __restrict__ out)
{
    __shared__ unsigned char bp[TT * NN];
    const int b = blockIdx.x;

    const uint4* src = (const uint4*)(g_bp + (size_t)b * ((size_t)TT * NN));
    uint4* dst = (uint4*)bp;
    for (int i = threadIdx.x; i < (TT * NN) / 16; i += 256) dst[i] = src[i];
    __syncthreads();

    if (threadIdx.x == 0) {
        int i = g_idx[b];
        float* path = out + BB + (size_t)b * (TT + 1);
        path[TT] = (float)i;
        for (int t = TT - 1; t >= 0; t--) {
            i = bp[t * NN + i];
            path[t] = (float)i;
        }
    }
}

extern "C" void kernel_launch(void* const* d_in, const int* in_sizes, int n_in,
                              void* d_out, int out_size)
{
    const float* feat  = (const float*)d_in[0];
    const float* trans = (const float*)d_in[1];
    if (n_in >= 2 && in_sizes[0] == NN * NN) {
        feat  = (const float*)d_in[1];
        trans = (const float*)d_in[0];
    }
    float* out = (float*)d_out;

    viterbi_fused<<<FWD_BLOCKS, FWD_THREADS>>>(feat, trans, out);
    viterbi_back<<<BB, 256>>>(out);
}

// round 15
// speedup vs baseline: 1.1842x; 1.1842x over previous
#include <cuda_runtime.h>
#include <cuda_pipeline.h>
#include <cstdint>
#include <cstddef>

#define BB 1024
#define TT 1024
#define NN 34
#define BPB 2
#define FWD_THREADS (BPB * NN)     // 68
#define FWD_BLOCKS  592            // 4 CTAs/SM balanced; tail clamps (idempotent)

#define CH 8                       // t-steps per bp chunk
#define NCH (TT / CH)              // 128
#define NSLOT 5
#define BPT_THREADS (CH * NN)      // 272
#define SROW 36                    // padded S row (floats) in smem, 144B

// Score history: row r of batch b = S_{r-1} (row 0 = init). [B][T+1][N]
__device__ float g_S[(size_t)BB * (TT + 1) * NN];
__device__ int g_idx[BB];

__device__ __forceinline__ unsigned long long addx2(unsigned long long a, unsigned long long b) {
    unsigned long long r;
    asm("add.rn.f32x2 %0, %1, %2;" : "=l"(r) : "l"(a), "l"(b));
    return r;
}
__device__ __forceinline__ unsigned long long packff(float f) {
    unsigned long long r; unsigned u = __float_as_uint(f);
    asm("mov.b64 %0, {%1, %1};" : "=l"(r) : "r"(u));
    return r;
}
__device__ __forceinline__ void unpk(unsigned long long v, float& lo, float& hi) {
    unsigned a, b;
    asm("mov.b64 {%0, %1}, %2;" : "=r"(a), "=r"(b) : "l"(v));
    lo = __uint_as_float(a); hi = __uint_as_float(b);
}

// ---------------- forward: f32x2 adds + scalar FMNMX tree (proven) ----------------
__global__ __launch_bounds__(FWD_THREADS)
void viterbi_fwd(const float* __restrict__ feat,
                 const float* __restrict__ trans,
                 float* __restrict__ out)
{
    const int tid = threadIdx.x;
    const int bl  = tid / NN;
    const int j   = tid % NN;
    int b = blockIdx.x * BPB + bl;
    if (b >= BB) b = BB - 1;

    __shared__ __align__(16) float sc[2][BPB][36];
    __shared__ float tend[NN];
    __shared__ float fin[BPB][NN];

    unsigned long long trp[17];
#pragma unroll
    for (int i = 0; i < 17; i++) {
        unsigned lo = __float_as_uint(trans[j * NN + 2 * i]);
        unsigned hi = __float_as_uint(trans[j * NN + 2 * i + 1]);
        asm("mov.b64 %0, {%1, %2};" : "=l"(trp[i]) : "r"(lo), "r"(hi));
    }
    if (tid < NN) tend[tid] = trans[(NN - 1) * NN + tid];

    const float init = (j == NN - 2) ? 0.0f : -6969.0f;
    sc[0][bl][j] = init;
    g_S[((size_t)b * (TT + 1)) * NN + j] = init;
    __syncthreads();

    const size_t fbase = (size_t)b * ((size_t)TT * NN) + j;
    const float* fp = feat + fbase;
    float* sp_out = g_S + ((size_t)b * (TT + 1) + 1) * NN + j;

    float fring[4];
#pragma unroll
    for (int u = 0; u < 4; u++) fring[u] = __ldg(fp + (size_t)u * NN);
    fp += (size_t)4 * NN;

    int cur = 0;
#pragma unroll 1
    for (int tb = 0; tb < TT; tb += 4) {
#pragma unroll
        for (int u = 0; u < 4; u++) {
            const int t = tb + u;
            float f = fring[u];
            float fn = 0.0f;
            if (t + 4 < TT) fn = __ldg(fp);
            fp += NN;
            fring[u] = fn;

            const ulonglong2* sp2 = (const ulonglong2*)&sc[cur][bl][0];
            unsigned long long ff = packff(f);

            float m[NN];
#pragma unroll
            for (int i = 0; i < 8; i++) {
                ulonglong2 q = sp2[i];
                unsigned long long v0 = addx2(addx2(q.x, ff), trp[2 * i]);
                unsigned long long v1 = addx2(addx2(q.y, ff), trp[2 * i + 1]);
                unpk(v0, m[4 * i], m[4 * i + 1]);
                unpk(v1, m[4 * i + 2], m[4 * i + 3]);
            }
            {
                unsigned long long q = *(const unsigned long long*)&sc[cur][bl][32];
                unsigned long long v = addx2(addx2(q, ff), trp[16]);
                unpk(v, m[32], m[33]);
            }
#pragma unroll
            for (int s = 1; s < NN; s <<= 1)
#pragma unroll
                for (int k = 0; k + s < NN; k += (s << 1))
                    m[k] = fmaxf(m[k], m[k + s]);

            sc[cur ^ 1][bl][j] = m[0];
            *sp_out = m[0];
            sp_out += NN;
            cur ^= 1;
            __syncthreads();
        }
    }

    fin[bl][j] = sc[cur][bl][j] + tend[j];
    __syncthreads();
    if (j == 0) {
        float bm = -3.4e38f; int bi = 0;
#pragma unroll
        for (int k = 0; k < NN; k++) {
            float v = fin[bl][k];
            if (v > bm) { bm = v; bi = k; }
        }
        out[b] = bm;
        g_idx[b] = bi;
    }
}

// -------- bp-build + chase fused: padded LDS128 rows, sel-chain select --------
#define SSEG_SRC (((CH + 1) * NN) / 2)   // 153 8B units from global
#define FSEG_SRC ((CH * NN) / 2)         // 136 8B units

__global__ __launch_bounds__(BPT_THREADS)
void bp_chase(const float* __restrict__ feat,
              const float* __restrict__ trans,
              float* __restrict__ out)
{
    const int b   = blockIdx.x;
    const int tid = threadIdx.x;
    const int s   = tid / NN;       // t-slot 0..7
    const int j   = tid % NN;

    __shared__ __align__(16) float SBUF[NSLOT][(CH + 1) * SROW];  // padded rows
    __shared__ __align__(16) float FBUF[NSLOT][CH * NN];
    __shared__ unsigned char bp[TT * NN];

    unsigned long long trp[17];
#pragma unroll
    for (int i = 0; i < 17; i++) {
        unsigned lo = __float_as_uint(trans[j * NN + 2 * i]);
        unsigned hi = __float_as_uint(trans[j * NN + 2 * i + 1]);
        asm("mov.b64 %0, {%1, %2};" : "=l"(trp[i]) : "r"(lo), "r"(hi));
    }

    const float* Sb = g_S + (size_t)b * (TT + 1) * NN;
    const float* Fb = feat + (size_t)b * TT * NN;

    auto stage = [&](int c) {
        const int sl = c % NSLOT;
        const double* sS = (const double*)(Sb + (size_t)c * CH * NN);
        double* dS = (double*)SBUF[sl];
        for (int i = tid; i < SSEG_SRC; i += BPT_THREADS) {
            int row = i / 17, col = i - row * 17;
            __pipeline_memcpy_async(dS + row * (SROW / 2) + col, sS + i, 8);
        }
        const double* sF = (const double*)(Fb + (size_t)c * CH * NN);
        double* dF = (double*)FBUF[sl];
        for (int i = tid; i < FSEG_SRC; i += BPT_THREADS)
            __pipeline_memcpy_async(dF + i, sF + i, 8);
        __pipeline_commit();
    };

#pragma unroll
    for (int c = 0; c < 4; c++) stage(c);

#pragma unroll 1
    for (int c = 0; c < NCH; c++) {
        const int sl = c % NSLOT;
        __pipeline_wait_prior(3);
        __syncthreads();
        if (c + 4 < NCH) stage(c + 4);

        const float f   = FBUF[sl][s * NN + j];
        const float tgt = SBUF[sl][(s + 1) * SROW + j];   // S_t[j]
        unsigned long long ff = packff(f);

        const ulonglong2* srow = (const ulonglong2*)&SBUF[sl][s * SROW]; // 16B-aligned
        float cand[NN];
#pragma unroll
        for (int i = 0; i < 8; i++) {
            ulonglong2 q = srow[i];
            unsigned long long v0 = addx2(addx2(q.x, ff), trp[2 * i]);
            unsigned long long v1 = addx2(addx2(q.y, ff), trp[2 * i + 1]);
            unpk(v0, cand[4 * i], cand[4 * i + 1]);
            unpk(v1, cand[4 * i + 2], cand[4 * i + 3]);
        }
        {
            ulonglong2 q = srow[8];                       // floats 32..35 (34,35 pad)
            unsigned long long v = addx2(addx2(q.x, ff), trp[16]);
            unpk(v, cand[32], cand[33]);
        }

        // smallest matching k via predicated select chain (count-optimal)
        int e = 33;
#pragma unroll
        for (int k = 33; k >= 0; k--)
            e = (cand[k] == tgt) ? k : e;

        bp[(c * CH + s) * NN + j] = (unsigned char)e;
    }

    __syncthreads();

    if (tid == 0) {
        int i = g_idx[b];
        float* path = out + BB + (size_t)b * (TT + 1);
        path[TT] = (float)i;
        for (int t = TT - 1; t >= 0; t--) {
            i = bp[t * NN + i];
            path[t] = (float)i;
        }
    }
}

extern "C" void kernel_launch(void* const* d_in, const int* in_sizes, int n_in,
                              void* d_out, int out_size)
{
    const float* feat  = (const float*)d_in[0];
    const float* trans = (const float*)d_in[1];
    if (n_in >= 2 && in_sizes[0] == NN * NN) {
        feat  = (const float*)d_in[1];
        trans = (const float*)d_in[0];
    }
    float* out = (float*)d_out;

    viterbi_fwd<<<FWD_BLOCKS, FWD_THREADS>>>(feat, trans, out);
    bp_chase<<<BB, BPT_THREADS>>>(feat, trans, out);
}

// round 17
// speedup vs baseline: 1.6721x; 1.4120x over previous
#include <cuda_runtime.h>
#include <cstdint>
#include <cstddef>

#define BB 1024
#define TT 1024
#define NN 34
#define BPB 2
#define FWD_THREADS (BPB * NN)     // 68
#define FWD_BLOCKS  592            // 4 CTAs/SM balanced; tail clamps (idempotent)

// Backpointers u8 [b][t][j]; final argmax per batch.
__device__ unsigned char g_bp[(size_t)BB * TT * NN];
__device__ int g_idx[BB];

__device__ __forceinline__ unsigned long long addx2(unsigned long long a, unsigned long long b) {
    unsigned long long r;
    asm("add.rn.f32x2 %0, %1, %2;" : "=l"(r) : "l"(a), "l"(b));
    return r;
}
__device__ __forceinline__ unsigned long long fmax2_fma(unsigned long long c,
                                                        unsigned long long negone,
                                                        unsigned long long m0p) {
    // returns m0 - c per lane: fma(c, -1, m0)
    unsigned long long r;
    asm("fma.rn.f32x2 %0, %1, %2, %3;" : "=l"(r) : "l"(c), "l"(negone), "l"(m0p));
    return r;
}
__device__ __forceinline__ unsigned long long packff(float f) {
    unsigned long long r; unsigned u = __float_as_uint(f);
    asm("mov.b64 %0, {%1, %1};" : "=l"(r) : "r"(u));
    return r;
}
__device__ __forceinline__ void unpk(unsigned long long v, float& lo, float& hi) {
    unsigned a, b;
    asm("mov.b64 {%0, %1}, %2;" : "=r"(a), "=r"(b) : "l"(v));
    lo = __uint_as_float(a); hi = __uint_as_float(b);
}
__device__ __forceinline__ void unpku(unsigned long long v, unsigned& lo, unsigned& hi) {
    asm("mov.b64 {%0, %1}, %2;" : "=r"(lo), "=r"(hi) : "l"(v));
}

// Forward with inline backpointer extraction (max-residual OR trick).
__global__ __launch_bounds__(FWD_THREADS)
void viterbi_fwd(const float* __restrict__ feat,
                 const float* __restrict__ trans,
                 float* __restrict__ out)
{
    const int tid = threadIdx.x;
    const int bl  = tid / NN;
    const int j   = tid % NN;
    int b = blockIdx.x * BPB + bl;
    if (b >= BB) b = BB - 1;       // tail CTAs duplicate batch 1023: identical writes, benign

    __shared__ __align__(16) float sc[2][BPB][36];
    __shared__ float tend[NN];
    __shared__ float fin[BPB][NN];

    // trans row j packed as f32x2 pairs
    unsigned long long trp[17];
#pragma unroll
    for (int i = 0; i < 17; i++) {
        unsigned lo = __float_as_uint(trans[j * NN + 2 * i]);
        unsigned hi = __float_as_uint(trans[j * NN + 2 * i + 1]);
        asm("mov.b64 %0, {%1, %2};" : "=l"(trp[i]) : "r"(lo), "r"(hi));
    }
    if (tid < NN) tend[tid] = trans[(NN - 1) * NN + tid];

    const unsigned long long negone = packff(-1.0f);

    const float init = (j == NN - 2) ? 0.0f : -6969.0f;
    sc[0][bl][j] = init;
    __syncthreads();

    const size_t fbase = (size_t)b * ((size_t)TT * NN) + j;
    const float* fp = feat + fbase;
    unsigned char* bpp = g_bp + (size_t)b * ((size_t)TT * NN) + j;

    // 4-deep feat prefetch ring
    float fring[4];
#pragma unroll
    for (int u = 0; u < 4; u++) fring[u] = __ldg(fp + (size_t)u * NN);
    fp += (size_t)4 * NN;

    int cur = 0;
#pragma unroll 1
    for (int tb = 0; tb < TT; tb += 4) {
#pragma unroll
        for (int u = 0; u < 4; u++) {
            const int t = tb + u;
            float f = fring[u];
            float fn = 0.0f;
            if (t + 4 < TT) fn = __ldg(fp);
            fp += NN;
            fring[u] = fn;

            const ulonglong2* sp2 = (const ulonglong2*)&sc[cur][bl][0];
            unsigned long long ff = packff(f);

            // packed candidates cp[i] = (s_pair + f) + tr_pair  (XLA association)
            unsigned long long cp[17];
#pragma unroll
            for (int i = 0; i < 8; i++) {
                ulonglong2 q = sp2[i];
                cp[2 * i]     = addx2(addx2(q.x, ff), trp[2 * i]);
                cp[2 * i + 1] = addx2(addx2(q.y, ff), trp[2 * i + 1]);
            }
            {
                unsigned long long q = *(const unsigned long long*)&sc[cur][bl][32];
                cp[16] = addx2(addx2(q, ff), trp[16]);
            }

            // exact max tree over unpacked views (cp[] stays alive)
            float m[NN];
#pragma unroll
            for (int i = 0; i < 17; i++) unpk(cp[i], m[2 * i], m[2 * i + 1]);
#pragma unroll
            for (int s = 1; s < NN; s <<= 1)
#pragma unroll
                for (int k = 0; k + s < NN; k += (s << 1))
                    m[k] = fmaxf(m[k], m[k + s]);
            const float m0 = m[0];

            // critical chain: publish and barrier
            sc[cur ^ 1][bl][j] = m0;
            cur ^= 1;
            __syncthreads();

            // off-chain (regs only): bp = smallest k with c[k]==m0.
            // d = m0 - c >= 0, ==+0 iff match; key = bits(d) | k; min-key low bits = k.
            const unsigned long long m0p = packff(m0);
            unsigned key[NN];
#pragma unroll
            for (int i = 0; i < 17; i++) {
                unsigned long long d = fmax2_fma(cp[i], negone, m0p);
                unsigned dlo, dhi;
                unpku(d, dlo, dhi);
                key[2 * i]     = dlo | (unsigned)(2 * i);
                key[2 * i + 1] = dhi | (unsigned)(2 * i + 1);
            }
#pragma unroll
            for (int s = 1; s < NN; s <<= 1)
#pragma unroll
                for (int k = 0; k + s < NN; k += (s << 1))
                    key[k] = key[k] < key[k + s] ? key[k] : key[k + s];

            *bpp = (unsigned char)(key[0] & 63u);
            bpp += NN;
        }
    }

    fin[bl][j] = sc[cur][bl][j] + tend[j];
    __syncthreads();
    if (j == 0) {
        float bm = -3.4e38f; int bi = 0;
#pragma unroll
        for (int k = 0; k < NN; k++) {
            float v = fin[bl][k];
            if (v > bm) { bm = v; bi = k; }
        }
        out[b] = bm;
        g_idx[b] = bi;
    }
}

// Proven chase (~48 us): stage bp table in smem, thread 0 walks it.
__global__ __launch_bounds__(256)
void viterbi_back(float* __restrict__ out)
{
    __shared__ unsigned char bp[TT * NN];
    const int b = blockIdx.x;

    const uint4* src = (const uint4*)(g_bp + (size_t)b * ((size_t)TT * NN));
    uint4* dst = (uint4*)bp;
    for (int i = threadIdx.x; i < (TT * NN) / 16; i += 256) dst[i] = src[i];
    __syncthreads();

    if (threadIdx.x == 0) {
        int i = g_idx[b];
        float* path = out + BB + (size_t)b * (TT + 1);
        path[TT] = (float)i;
        for (int t = TT - 1; t >= 0; t--) {
            i = bp[t * NN + i];
            path[t] = (float)i;
        }
    }
}

extern "C" void kernel_launch(void* const* d_in, const int* in_sizes, int n_in,
                              void* d_out, int out_size)
{
    const float* feat  = (const float*)d_in[0];
    const float* trans = (const float*)d_in[1];
    if (n_in >= 2 && in_sizes[0] == NN * NN) {
        feat  = (const float*)d_in[1];
        trans = (const float*)d_in[0];
    }
    float* out = (float*)d_out;

    viterbi_fwd<<<FWD_BLOCKS, FWD_THREADS>>>(feat, trans, out);
    viterbi_back<<<BB, 256>>>(out);
}